// round 11
// baseline (speedup 1.0000x reference)
#include <cuda_runtime.h>
#include <cstdint>

#define NGATE 128
#define NBLK  129
#define NTHR  128
#define HID   512
#define BB    32
#define TT    32
#define INF_  397
#define NOUT  129

#define LOGITS_ELEMS 132096
#define HC_ELEMS     16384

// smem floats: sW 8192 | sh 20480 | sred 128 | sE 8
#define SMEM_FLOATS 28840
#define SMEM_BYTES  (SMEM_FLOATS * 4)

__device__ __align__(16) float g_pre[TT * 2048 * BB];   // [t][row][b]
__device__ __align__(16) float g_h[HID * BB];           // h, PAIR-PACKED [kp][b][2]
__device__ __align__(16) float g_th[HID * BB];          // tanh(h), [k][b]
__device__ __align__(16) unsigned long long g_best[TT][BB];  // packed argmax keys
__device__ __align__(128) unsigned g_hdone[TT];  // monotonic: +NGATE per launch per slot
__device__ __align__(128) unsigned g_done[TT];   // monotonic: +NBLK  per launch per slot (t<TT-1)
__device__ __align__(128) unsigned g_epoch;      // monotonic launch counter; read at start

__device__ __forceinline__ float sigm(float x) { return 1.f / (1.f + __expf(-x)); }
__device__ __forceinline__ float tanh_p(float x) {
    float e = __expf(-2.f * fabsf(x));
    float r = (1.f - e) / (1.f + e);
    return copysignf(r, x);
}
__device__ __forceinline__ void ffma2u(unsigned long long& acc, unsigned long long w, unsigned long long h) {
    asm volatile("fma.rn.f32x2 %0, %1, %2, %0;" : "+l"(acc) : "l"(w), "l"(h));
}
__device__ __forceinline__ float2 unpack2(unsigned long long v) {
    float2 r; asm("mov.b64 {%0, %1}, %2;" : "=f"(r.x), "=f"(r.y) : "l"(v)); return r;
}
// monotone f32->u32 order embedding; key = (mkey << 32) | (255 - o):
// max key == max logit, ties -> smallest o == first-max == jnp.argmax.
__device__ __forceinline__ unsigned long long pack_key(float f, int o) {
    unsigned u = __float_as_uint(f);
    u = (u & 0x80000000u) ? ~u : (u | 0x80000000u);
    return (((unsigned long long)u) << 32) | (unsigned)(255 - o);
}
__device__ __forceinline__ void rel_add(unsigned* p) {
    asm volatile("red.release.gpu.global.add.u32 [%0], 1;" :: "l"(p) : "memory");
}
__device__ __forceinline__ void acq_poll(const unsigned* p, unsigned want) {
    unsigned v;
    do {
        asm volatile("ld.acquire.gpu.global.u32 %0, [%1];" : "=r"(v) : "l"(p) : "memory");
    } while ((int)(v - want) < 0);
}

__global__ void __launch_bounds__(NTHR, 1)
decoder_kernel(const float* __restrict__ chords, const float* __restrict__ latent,
               const float* __restrict__ W_ih, const float* __restrict__ W_hh,
               const float* __restrict__ b_ih, const float* __restrict__ b_hh,
               const float* __restrict__ W_lin, const float* __restrict__ b_lin,
               float* __restrict__ out, int out_size)
{
    extern __shared__ float smem[];
    float* sW   = smem;                  // 8192
    float* sh   = smem + 8192;           // 20480
    float* sred = smem + 8192 + 20480;   // 128
    unsigned* sE = (unsigned*)(sred + 128 + 32);

    const int tid  = threadIdx.x;
    const int lane = tid & 31;
    const int wid  = tid >> 5;
    const int bid  = blockIdx.x;         // 0..128; bid==128 is logits-only
    const int j    = (bid << 2) + wid;   // hidden unit (valid for bid < 128)

    if (tid == 0) {
        unsigned e0;
        asm volatile("ld.acquire.gpu.global.u32 %0, [%1];"
                     : "=r"(e0) : "l"(&g_epoch) : "memory");
        sE[0] = e0;                      // stable: next launch starts only after this exits
    }
    // per-launch reset of argmax keys (slot t=bid). Visible to any reader of
    // g_best[t] because readers first acquire g_hdone[t] >= all-gates, which
    // includes this CTA's release — ordered after these plain stores.
    if (bid < TT && tid < BB) g_best[bid][tid] = 0ull;

    if (bid < NGATE) {
        // ---- Stage W_hh rows into smem ----
        {
            float* dst = sW + wid * 2048;
            #pragma unroll
            for (int g = 0; g < 4; ++g) {
                const float* src = W_hh + (size_t)(g * HID + j) * HID;
                for (int k = (lane << 2); k < 512; k += 128)
                    *(float4*)(dst + g * 512 + k) = *(const float4*)(src + k);
            }
        }
        for (int i = tid; i < BB * 256; i += NTHR) {
            int b = i >> 8, l = i & 255;
            sh[l * 32 + b] = latent[i];
        }
        {
            float* sch = sh + 8192;
            for (int i = tid; i < BB * TT * 12; i += NTHR) {
                int b = i / 384, rem = i - b * 384;
                sch[rem * 32 + b] = chords[i];
            }
        }
        __syncthreads();

        // ---- Precompute g_pre[t][row][b] (own rows only; read back by self) ----
        {
            const float* sch = sh + 8192;
            #pragma unroll
            for (int g = 0; g < 4; ++g) {
                const int row = g * HID + j;
                const float* wrow = W_ih + (size_t)row * INF_;
                float acc = __ldg(b_ih + row) + __ldg(b_hh + row);
                #pragma unroll 8
                for (int k = 0; k < 256; ++k)
                    acc = fmaf(sh[k * 32 + lane], __ldg(wrow + k), acc);
                float wc[12];
                #pragma unroll
                for (int cc = 0; cc < 12; ++cc) wc[cc] = __ldg(wrow + 385 + cc);
                for (int t = 0; t < TT; ++t) {
                    float z = acc;
                    #pragma unroll
                    for (int cc = 0; cc < 12; ++cc)
                        z = fmaf(sch[(t * 12 + cc) * 32 + lane], wc[cc], z);
                    g_pre[((size_t)(t * 2048) + row) * 32 + lane] = z;
                }
            }
        }
        __syncthreads();
    } else {
        __syncthreads();
    }
    const unsigned ep0 = sE[0];
    const unsigned HT = ep0 * NGATE + NGATE;   // per-slot g_hdone target this launch
    const unsigned DT = ep0 * NBLK + NBLK;     // per-slot g_done target this launch

    const int r0 = j, r1 = HID + j, r2 = 2 * HID + j, r3 = 3 * HID + j;
    const float* w0 = sW + wid * 2048;
    const float* w1 = w0 + 512;
    const float* w2 = w0 + 1024;
    const float* w3 = w0 + 1536;

    float creg = 0.f;

    for (int t = 0; t < TT; ++t) {
        if (bid < NGATE) {
            __syncthreads();   // sh holds h(t-1); staging STS drained last iteration

            const float* prebase = g_pre + (size_t)(t * 2048) * 32;
            float zi = prebase[r0 * 32 + lane];
            float zf = prebase[r1 * 32 + lane];
            float zg = prebase[r2 * 32 + lane];
            float zo = prebase[r3 * 32 + lane];

            if (t > 0) {
                // ---- recurrent dot FIRST (doesn't need pidx) ----
                const unsigned long long* sh64 = (const unsigned long long*)sh;
                unsigned long long A0 = 0, A1 = 0, A2 = 0, A3 = 0;
                #pragma unroll 4
                for (int k = 0; k < 512; k += 4) {
                    const int kp = k >> 1;
                    unsigned long long h01 = sh64[kp * 32 + lane];
                    unsigned long long h23 = sh64[(kp + 1) * 32 + lane];
                    ulonglong2 Wa = *(const ulonglong2*)(w0 + k);
                    ulonglong2 Wb = *(const ulonglong2*)(w1 + k);
                    ulonglong2 Wc = *(const ulonglong2*)(w2 + k);
                    ulonglong2 Wd = *(const ulonglong2*)(w3 + k);
                    ffma2u(A0, Wa.x, h01); ffma2u(A1, Wb.x, h01);
                    ffma2u(A2, Wc.x, h01); ffma2u(A3, Wd.x, h01);
                    ffma2u(A0, Wa.y, h23); ffma2u(A1, Wb.y, h23);
                    ffma2u(A2, Wc.y, h23); ffma2u(A3, Wd.y, h23);
                }

                // ---- wait for argmax(t-1); this wait also guarantees all CTAs
                //      finished READING h(t-1)/th(t-1) -> safe to overwrite below
                if (tid == 0) acq_poll(&g_done[t - 1], DT);
                __syncthreads();
                unsigned long long key;
                asm volatile("ld.global.cg.u64 %0, [%1];"
                             : "=l"(key) : "l"(&g_best[t - 1][lane]) : "memory");
                const int pidx = 255 - (int)(unsigned)(key & 0xffu);

                zi += __ldg(W_ih + (size_t)r0 * INF_ + 256 + pidx);
                zf += __ldg(W_ih + (size_t)r1 * INF_ + 256 + pidx);
                zg += __ldg(W_ih + (size_t)r2 * INF_ + 256 + pidx);
                zo += __ldg(W_ih + (size_t)r3 * INF_ + 256 + pidx);
                float2 u0 = unpack2(A0), u1 = unpack2(A1);
                float2 u2 = unpack2(A2), u3 = unpack2(A3);
                zi += u0.x + u0.y; zf += u1.x + u1.y;
                zg += u2.x + u2.y; zo += u3.x + u3.y;
            }

            const float gi = sigm(zi), gf = sigm(zf), gg = tanh_p(zg), go = sigm(zo);
            creg = gf * creg + gi * gg;
            const float hv = go * tanh_p(creg);
            const float th = tanh_p(hv);
            g_h[(j >> 1) * 64 + lane * 2 + (j & 1)] = hv;   // pair-packed
            g_th[j * 32 + lane] = th;                       // [k][b]
            if (t == TT - 1 && out_size >= LOGITS_ELEMS + 2 * HC_ELEMS) {
                out[LOGITS_ELEMS + lane * HID + j]            = hv;
                out[LOGITS_ELEMS + HC_ELEMS + lane * HID + j] = creg;
            }
            __syncthreads();            // all 4 warps' h/th stores done
            if (tid == 0) {
                __threadfence();
                rel_add(&g_hdone[t]);   // publish this CTA's h(t)/th(t)
            }
        }

        // ---- wait until ALL gate CTAs published h(t)/th(t) ----
        if (tid == 0) acq_poll(&g_hdone[t], HT);
        __syncthreads();

        // ---- stage h(t) for next step's dot (gate CTAs; overlaps logits) ----
        if (bid < NGATE && t < TT - 1) {
            const float4* src4 = (const float4*)g_h;
            float4* dst4 = (float4*)sh;
            #pragma unroll 4
            for (int i = tid; i < HID * BB / 4; i += NTHR) dst4[i] = __ldcg(src4 + i);
        }

        // ---- logits column o = bid (all CTAs; arithmetic identical to R10) ----
        {
            const int o = bid;
            const float* wl  = W_lin + (size_t)o * HID + wid * 128;
            const float* thp = g_th + (wid * 128) * 32;
            float c0 = 0.f, c1 = 0.f, c2 = 0.f, c3 = 0.f;
            #pragma unroll
            for (int k = 0; k < 128; k += 4) {
                c0 = fmaf(__ldcg(thp + (k + 0) * 32 + lane), __ldg(wl + k + 0), c0);
                c1 = fmaf(__ldcg(thp + (k + 1) * 32 + lane), __ldg(wl + k + 1), c1);
                c2 = fmaf(__ldcg(thp + (k + 2) * 32 + lane), __ldg(wl + k + 2), c2);
                c3 = fmaf(__ldcg(thp + (k + 3) * 32 + lane), __ldg(wl + k + 3), c3);
            }
            sred[wid * 32 + lane] = (c0 + c1) + (c2 + c3);
            __syncthreads();   // drains staging STS (so h(t) reads are retired) + sred
            if (wid == 0) {
                float tot = sred[lane] + sred[32 + lane] + sred[64 + lane]
                          + sred[96 + lane] + __ldg(b_lin + o);
                out[lane * (TT * NOUT) + t * NOUT + o] = tot;
                if (t < TT - 1) {
                    unsigned long long key = pack_key(tot, o);
                    asm volatile("red.relaxed.gpu.global.max.u64 [%0], %1;"
                                 :: "l"(&g_best[t][lane]), "l"(key) : "memory");
                }
            }
            __syncthreads();
            if (t < TT - 1 && tid == 0) {
                __threadfence();
                rel_add(&g_done[t]);   // column done; also certifies gen-t reads done
            }
        }
    }

    // exactly one epoch bump per launch; provably after every CTA has read its
    // base (CTA0's t=31 poll of g_done[30] includes CTA128's release).
    if (bid == 0 && tid == 0) rel_add(&g_epoch);
}

extern "C" void kernel_launch(void* const* d_in, const int* in_sizes, int n_in,
                              void* d_out, int out_size) {
    const int want[8] = {12288, 8192, 813056, 1048576, 2048, 2048, 66048, 129};
    const float* p[8] = {nullptr, nullptr, nullptr, nullptr, nullptr, nullptr, nullptr, nullptr};
    bool used[64] = {false};
    for (int w = 0; w < 8; ++w) {
        for (int i = 0; i < n_in && i < 64; ++i) {
            if (!used[i] && in_sizes[i] == want[w]) {
                p[w] = (const float*)d_in[i];
                used[i] = true;
                break;
            }
        }
    }
    cudaFuncSetAttribute(decoder_kernel, cudaFuncAttributeMaxDynamicSharedMemorySize, SMEM_BYTES);
    decoder_kernel<<<NBLK, NTHR, SMEM_BYTES>>>(p[0], p[1], p[2], p[3], p[4], p[5], p[6], p[7],
                                               (float*)d_out, out_size);
}